// round 2
// baseline (speedup 1.0000x reference)
#include <cuda_runtime.h>

// CutStripes: out[b, :, t, :] = x[perm[b], :, t, :] if t falls inside any of 4
// stripes [bgn[b,s], bgn[b,s]+distance[b,s]), else x[b, :, t, :].
// Shapes fixed by the problem: B=128, C=1, T=2048, F=128, STRIPES=4.
//
// Strategy: 1 warp per (b, t) row. Row = 128 fp32 = 32 float4 = one lane each.
// Lanes 0..3 evaluate the 4 stripe intervals; ballot -> row mask; copy row
// from the selected source batch. Pure streaming copy, HBM-bound.

#define T_DIM   2048
#define F4      32          // 128 floats / 4
#define STRIPES 4

__global__ __launch_bounds__(256) void cutstripes_kernel(
    const float4* __restrict__ x,
    const int*    __restrict__ perm,
    const int*    __restrict__ bgn,
    const int*    __restrict__ dist,
    float4*       __restrict__ out)
{
    const int warp = (blockIdx.x * blockDim.x + threadIdx.x) >> 5;  // row id in [0, B*T)
    const int lane = threadIdx.x & 31;

    const int b = warp >> 11;        // / T_DIM
    const int t = warp & (T_DIM - 1);

    bool in_stripe = false;
    if (lane < STRIPES) {
        const int lo = __ldg(&bgn[b * STRIPES + lane]);
        const int hi = lo + __ldg(&dist[b * STRIPES + lane]);
        in_stripe = (t >= lo) && (t < hi);
    }
    const unsigned m = __ballot_sync(0xFFFFFFFFu, in_stripe);
    const int src = m ? __ldg(&perm[b]) : b;

    const int dst_idx = ((b   << 11) | t) * F4 + lane;
    const int src_idx = ((src << 11) | t) * F4 + lane;

    out[dst_idx] = x[src_idx];
}

extern "C" void kernel_launch(void* const* d_in, const int* in_sizes, int n_in,
                              void* d_out, int out_size)
{
    const float4* x    = (const float4*)d_in[0];   // (128,1,2048,128) fp32
    const int*    perm = (const int*)   d_in[1];   // (128,)
    const int*    bgn  = (const int*)   d_in[2];   // (128,4)
    const int*    dist = (const int*)   d_in[3];   // (128,4)
    float4*       out  = (float4*)d_out;

    // B*T rows = 262144 warps; 8 warps per 256-thread block.
    const int rows   = 128 * T_DIM;
    const int blocks = rows / 8;

    cutstripes_kernel<<<blocks, 256>>>(x, perm, bgn, dist, out);
}

// round 3
// speedup vs baseline: 1.1004x; 1.1004x over previous
#include <cuda_runtime.h>

// CutStripes: out[b, :, t, :] = x[perm[b], :, t, :] if t falls inside any of 4
// stripes [bgn[b,s], bgn[b,s]+distance[b,s]), else x[b, :, t, :].
// Shapes: B=128, C=1, T=2048, F=128, STRIPES=4.
//
// R2: one warp handles 8 consecutive t-rows (4 KB contiguous). Each thread
// front-batches 8 independent LDG.128s into registers (MLP_p1=8), then issues
// 8 STG.128s. The 8x4=32 stripe checks map one per lane -> single ballot.

#define T_DIM     2048
#define F4        32        // 128 floats / 4
#define STRIPES   4
#define ROWS_PER_WARP 8

__global__ __launch_bounds__(256) void cutstripes_kernel(
    const float4* __restrict__ x,
    const int*    __restrict__ perm,
    const int*    __restrict__ bgn,
    const int*    __restrict__ dist,
    float4*       __restrict__ out)
{
    const int warp = (blockIdx.x * blockDim.x + threadIdx.x) >> 5;  // row-group id
    const int lane = threadIdx.x & 31;

    // Each group = 8 consecutive t rows of one batch b.
    const int groups_per_b = T_DIM / ROWS_PER_WARP;   // 256
    const int b  = warp >> 8;                          // / groups_per_b
    const int t0 = (warp & (groups_per_b - 1)) * ROWS_PER_WARP;

    // Lane l checks row k = l>>2, stripe s = l&3.
    {
        const int k = lane >> 2;
        const int s = lane & 3;
        const int lo = __ldg(&bgn[b * STRIPES + s]);
        const int hi = lo + __ldg(&dist[b * STRIPES + s]);
        const int t  = t0 + k;
        const bool in_stripe = (t >= lo) && (t < hi);
        const unsigned m = __ballot_sync(0xFFFFFFFFu, in_stripe);
        const int pb = __ldg(&perm[b]);

        // Front-batched loads: 8 independent LDG.128.
        float4 v[ROWS_PER_WARP];
        #pragma unroll
        for (int r = 0; r < ROWS_PER_WARP; r++) {
            const int src = ((m >> (4 * r)) & 0xF) ? pb : b;
            const long src_idx = ((long)(src << 11 | (t0 + r))) * F4 + lane;
            v[r] = x[src_idx];
        }

        // Stores: 8 STG.128, fully coalesced (warp writes 4 KB contiguous).
        const long dst_base = ((long)(b << 11 | t0)) * F4 + lane;
        #pragma unroll
        for (int r = 0; r < ROWS_PER_WARP; r++) {
            out[dst_base + (long)r * F4] = v[r];
        }
    }
}

extern "C" void kernel_launch(void* const* d_in, const int* in_sizes, int n_in,
                              void* d_out, int out_size)
{
    const float4* x    = (const float4*)d_in[0];   // (128,1,2048,128) fp32
    const int*    perm = (const int*)   d_in[1];   // (128,)
    const int*    bgn  = (const int*)   d_in[2];   // (128,4)
    const int*    dist = (const int*)   d_in[3];   // (128,4)
    float4*       out  = (float4*)d_out;

    const int rows   = 128 * T_DIM;                   // 262144
    const int warps  = rows / ROWS_PER_WARP;          // 32768
    const int blocks = warps / 8;                     // 4096 blocks of 256 thr

    cutstripes_kernel<<<blocks, 256>>>(x, perm, bgn, dist, out);
}

// round 4
// speedup vs baseline: 1.1339x; 1.0305x over previous
#include <cuda_runtime.h>
#include <cstdint>

// CutStripes: out[b, :, t, :] = x[perm[b], :, t, :] if t falls inside any of 4
// stripes [bgn[b,s], bgn[b,s]+distance[b,s]), else x[b, :, t, :].
// Shapes: B=128, C=1, T=2048, F=128, STRIPES=4.
//
// R3: decouple loads from registers with cp.async (LDGSTS) staging through
// shared memory. Each thread fires 8 independent 16B async loads (no register
// destination -> guaranteed MLP=8/thread, 64/warp), waits, then reads back its
// own bytes and issues 8 coalesced STG.128. This defeats ptxas's 2-deep
// load/store pipelining that capped R2 at 68% DRAM.

#define T_DIM         2048
#define F4            32        // 128 floats / 4
#define STRIPES       4
#define ROWS_PER_WARP 8
#define WARPS_PER_BLK 8

__global__ __launch_bounds__(256) void cutstripes_kernel(
    const float4* __restrict__ x,
    const int*    __restrict__ perm,
    const int*    __restrict__ bgn,
    const int*    __restrict__ dist,
    float4*       __restrict__ out)
{
    // [warp][row][lane] : 8*8*32*16B = 32 KB. Conflict-free LDS.128.
    __shared__ float4 tile[WARPS_PER_BLK][ROWS_PER_WARP][32];

    const int warp = (blockIdx.x * blockDim.x + threadIdx.x) >> 5;  // row-group id
    const int lane = threadIdx.x & 31;
    const int wib  = threadIdx.x >> 5;

    // Each group = 8 consecutive t rows of one batch b.
    const int groups_per_b = T_DIM / ROWS_PER_WARP;   // 256
    const int b  = warp >> 8;                         // / groups_per_b
    const int t0 = (warp & (groups_per_b - 1)) * ROWS_PER_WARP;

    // Lane l checks row k = l>>2, stripe s = l&3 -> one ballot covers all 8 rows.
    const int k = lane >> 2;
    const int s = lane & 3;
    const int lo = __ldg(&bgn[b * STRIPES + s]);
    const int hi = lo + __ldg(&dist[b * STRIPES + s]);
    const bool in_stripe = ((t0 + k) >= lo) && ((t0 + k) < hi);
    const unsigned m = __ballot_sync(0xFFFFFFFFu, in_stripe);
    const int pb = __ldg(&perm[b]);

    // Fire 8 async 16B loads, registers never touched.
    uint32_t smem_base = (uint32_t)__cvta_generic_to_shared(&tile[wib][0][lane]);
    #pragma unroll
    for (int r = 0; r < ROWS_PER_WARP; r++) {
        const int src = ((m >> (4 * r)) & 0xF) ? pb : b;
        const float4* gsrc = x + ((long)(src << 11 | (t0 + r)) * F4 + lane);
        asm volatile("cp.async.cg.shared.global [%0], [%1], 16;\n"
                     :: "r"(smem_base + r * (32 * 16)), "l"(gsrc));
    }
    asm volatile("cp.async.commit_group;\n" ::: "memory");
    asm volatile("cp.async.wait_group 0;\n" ::: "memory");

    // Read back own bytes (no __syncthreads needed) and store coalesced.
    const long dst_base = (long)(b << 11 | t0) * F4 + lane;
    #pragma unroll
    for (int r = 0; r < ROWS_PER_WARP; r++) {
        out[dst_base + (long)r * F4] = tile[wib][r][lane];
    }
}

extern "C" void kernel_launch(void* const* d_in, const int* in_sizes, int n_in,
                              void* d_out, int out_size)
{
    const float4* x    = (const float4*)d_in[0];   // (128,1,2048,128) fp32
    const int*    perm = (const int*)   d_in[1];   // (128,)
    const int*    bgn  = (const int*)   d_in[2];   // (128,4)
    const int*    dist = (const int*)   d_in[3];   // (128,4)
    float4*       out  = (float4*)d_out;

    const int rows   = 128 * T_DIM;                   // 262144
    const int warps  = rows / ROWS_PER_WARP;          // 32768
    const int blocks = warps / WARPS_PER_BLK;         // 4096

    cutstripes_kernel<<<blocks, 256>>>(x, perm, bgn, dist, out);
}